// round 7
// baseline (speedup 1.0000x reference)
#include <cuda_runtime.h>
#include <cuda_bf16.h>
#include <cuda_fp16.h>
#include <cstdint>

#define NN      100000
#define EE      1600000
#define INDIM   512
#define HID     64
#define NCLS    16
#define NCH     ((NN + 1023) / 1024)     // 98 scan chunks

// ---------------- scratch (static device globals; no allocation) -------------
__device__ float g_deg[NN];
__device__ float g_dis[NN];
__device__ float g_selfnorm[NN];
__device__ __half g_h1h[(size_t)NN * HID];
__device__ __half g_h2h[(size_t)NN * NCLS];
__device__ int   g_count[NN];
__device__ int   g_off[NN];
__device__ int   g_cursor[NN];
__device__ int   g_bsum[128];
__device__ int   g_bcarry[128];
__device__ int2  g_edge[EE];             // (src, full-norm bits) sorted by dst
__device__ __nv_bfloat16 g_w1t_hi[HID * INDIM];
__device__ __nv_bfloat16 g_w1t_lo[HID * INDIM];

// ---------------- helpers -----------------------------------------------------
__device__ __forceinline__ uint32_t packbf(float first, float second) {
    uint32_t r;
    asm("cvt.rn.bf16x2.f32 %0, %1, %2;" : "=r"(r) : "f"(second), "f"(first));
    return r;
}

__device__ __forceinline__ void mma_bf16(float& d0, float& d1, float& d2, float& d3,
                                         uint32_t a0, uint32_t a1, uint32_t a2, uint32_t a3,
                                         uint32_t b0, uint32_t b1) {
    asm volatile(
        "mma.sync.aligned.m16n8k16.row.col.f32.bf16.bf16.f32 "
        "{%0,%1,%2,%3}, {%4,%5,%6,%7}, {%8,%9}, {%0,%1,%2,%3};"
        : "+f"(d0), "+f"(d1), "+f"(d2), "+f"(d3)
        : "r"(a0), "r"(a1), "r"(a2), "r"(a3), "r"(b0), "r"(b1));
}

// ---------------- CSR build ---------------------------------------------------
__global__ void k_zero() {
    int i = blockIdx.x * blockDim.x + threadIdx.x;
    if (i < NN) { g_count[i] = 0; g_deg[i] = 1.0f; }   // self-loop weight
}

__global__ void k_hist(const int* __restrict__ dst, const float* __restrict__ ew) {
    int e = blockIdx.x * blockDim.x + threadIdx.x;
    if (e < EE) {
        int d = dst[e];
        atomicAdd(&g_count[d], 1);
        atomicAdd(&g_deg[d], ew[e]);
    }
}

__global__ void k_dis() {
    int i = blockIdx.x * blockDim.x + threadIdx.x;
    if (i < NN) {
        float r = rsqrtf(g_deg[i]);
        g_dis[i] = r;
        g_selfnorm[i] = r * r;
    }
}

__global__ void k_scan1() {
    __shared__ int sm[1024];
    int tid = threadIdx.x;
    int i = blockIdx.x * 1024 + tid;
    int v = (i < NN) ? g_count[i] : 0;
    sm[tid] = v;
    __syncthreads();
#pragma unroll
    for (int off = 1; off < 1024; off <<= 1) {
        int t = (tid >= off) ? sm[tid - off] : 0;
        __syncthreads();
        sm[tid] += t;
        __syncthreads();
    }
    if (i < NN) g_off[i] = sm[tid] - v;
    if (tid == 1023) g_bsum[blockIdx.x] = sm[tid];
}

__global__ void k_scan2() {
    __shared__ int sm[128];
    int tid = threadIdx.x;
    int v = (tid < NCH) ? g_bsum[tid] : 0;
    sm[tid] = v;
    __syncthreads();
#pragma unroll
    for (int off = 1; off < 128; off <<= 1) {
        int t = (tid >= off) ? sm[tid - off] : 0;
        __syncthreads();
        sm[tid] += t;
        __syncthreads();
    }
    g_bcarry[tid] = sm[tid] - v;
}

__global__ void k_scan3() {
    int i = blockIdx.x * blockDim.x + threadIdx.x;
    if (i < NN) {
        int o = g_off[i] + g_bcarry[i >> 10];
        g_off[i] = o;
        g_cursor[i] = o;
    }
}

__global__ void k_fill(const int* __restrict__ src, const int* __restrict__ dst,
                       const float* __restrict__ ew) {
    int e = blockIdx.x * blockDim.x + threadIdx.x;
    if (e >= EE) return;
    int s = src[e], d = dst[e];
    int pos = atomicAdd(&g_cursor[d], 1);
    float nm = g_dis[s] * ew[e] * g_dis[d];
    g_edge[pos] = make_int2(s, __float_as_int(nm));
}

// ---------------- W1^T split prep ---------------------------------------------
__global__ void k_prep_w(const float* __restrict__ W1) {
    int idx = blockIdx.x * blockDim.x + threadIdx.x;
    if (idx >= HID * INDIM) return;
    int n = idx >> 9;
    int k = idx & 511;
    float w = W1[k * HID + n];
    __nv_bfloat16 h = __float2bfloat16_rn(w);
    float hf = __bfloat162float(h);
    g_w1t_hi[n * INDIM + k] = h;
    g_w1t_lo[n * INDIM + k] = __float2bfloat16_rn(w - hf);
}

// ---------------- GEMM1 via mma.sync split-bf16 -> h1 (fp16) ------------------
#define KC     32
#define APITCH 40
#define APB    (APITCH * 2)

__global__ void __launch_bounds__(256)
k_gemm1_tc(const float* __restrict__ x) {
    __shared__ uint8_t As_hi[128 * APB];
    __shared__ uint8_t As_lo[128 * APB];
    __shared__ uint8_t Bs_hi[64 * APB];
    __shared__ uint8_t Bs_lo[64 * APB];

    int tid = threadIdx.x;
    int wid = tid >> 5;
    int lane = tid & 31;
    int lt = lane >> 2;
    int q  = lane & 3;
    int row0 = blockIdx.x * 128;

    float acc[8][4];
#pragma unroll
    for (int t = 0; t < 8; t++)
#pragma unroll
        for (int j = 0; j < 4; j++) acc[t][j] = 0.0f;

    const uint2* whi = reinterpret_cast<const uint2*>(g_w1t_hi);
    const uint2* wlo = reinterpret_cast<const uint2*>(g_w1t_lo);

    for (int k0 = 0; k0 < INDIM; k0 += KC) {
#pragma unroll
        for (int i = 0; i < 4; i++) {
            int idx = tid + i * 256;
            int r = idx >> 3;
            int c4 = (idx & 7) * 4;
            float4 v = make_float4(0.f, 0.f, 0.f, 0.f);
            int grow = row0 + r;
            if (grow < NN)
                v = *reinterpret_cast<const float4*>(&x[(size_t)grow * INDIM + k0 + c4]);
            uint32_t hp0 = packbf(v.x, v.y);
            uint32_t hp1 = packbf(v.z, v.w);
            float hx = __uint_as_float(hp0 << 16);
            float hy = __uint_as_float(hp0 & 0xFFFF0000u);
            float hz = __uint_as_float(hp1 << 16);
            float hw = __uint_as_float(hp1 & 0xFFFF0000u);
            uint32_t lp0 = packbf(v.x - hx, v.y - hy);
            uint32_t lp1 = packbf(v.z - hz, v.w - hw);
            uint32_t off = (uint32_t)(r * APB + c4 * 2);
            *reinterpret_cast<uint2*>(As_hi + off) = make_uint2(hp0, hp1);
            *reinterpret_cast<uint2*>(As_lo + off) = make_uint2(lp0, lp1);
        }
#pragma unroll
        for (int i = 0; i < 2; i++) {
            int idx = tid + i * 256;
            int n = idx >> 3;
            int j = idx & 7;
            int gidx = n * 128 + (k0 >> 2) + j;
            uint32_t off = (uint32_t)(n * APB + j * 8);
            *reinterpret_cast<uint2*>(Bs_hi + off) = whi[gidx];
            *reinterpret_cast<uint2*>(Bs_lo + off) = wlo[gidx];
        }
        __syncthreads();

#pragma unroll
        for (int ks = 0; ks < 2; ks++) {
            uint32_t abase = (uint32_t)((wid * 16 + lt) * APB + ks * 32 + q * 4);
            uint32_t ah0 = *reinterpret_cast<const uint32_t*>(As_hi + abase);
            uint32_t ah1 = *reinterpret_cast<const uint32_t*>(As_hi + abase + 8 * APB);
            uint32_t ah2 = *reinterpret_cast<const uint32_t*>(As_hi + abase + 16);
            uint32_t ah3 = *reinterpret_cast<const uint32_t*>(As_hi + abase + 8 * APB + 16);
            uint32_t al0 = *reinterpret_cast<const uint32_t*>(As_lo + abase);
            uint32_t al1 = *reinterpret_cast<const uint32_t*>(As_lo + abase + 8 * APB);
            uint32_t al2 = *reinterpret_cast<const uint32_t*>(As_lo + abase + 16);
            uint32_t al3 = *reinterpret_cast<const uint32_t*>(As_lo + abase + 8 * APB + 16);
#pragma unroll
            for (int nt = 0; nt < 8; nt++) {
                uint32_t bbase = (uint32_t)((nt * 8 + lt) * APB + ks * 32 + q * 4);
                uint32_t bh0 = *reinterpret_cast<const uint32_t*>(Bs_hi + bbase);
                uint32_t bh1 = *reinterpret_cast<const uint32_t*>(Bs_hi + bbase + 16);
                uint32_t bl0 = *reinterpret_cast<const uint32_t*>(Bs_lo + bbase);
                uint32_t bl1 = *reinterpret_cast<const uint32_t*>(Bs_lo + bbase + 16);
                mma_bf16(acc[nt][0], acc[nt][1], acc[nt][2], acc[nt][3],
                         ah0, ah1, ah2, ah3, bh0, bh1);
                mma_bf16(acc[nt][0], acc[nt][1], acc[nt][2], acc[nt][3],
                         ah0, ah1, ah2, ah3, bl0, bl1);
                mma_bf16(acc[nt][0], acc[nt][1], acc[nt][2], acc[nt][3],
                         al0, al1, al2, al3, bh0, bh1);
            }
        }
        __syncthreads();
    }

    int rA = row0 + wid * 16 + lt;
    int rB = rA + 8;
#pragma unroll
    for (int nt = 0; nt < 8; nt++) {
        int col = nt * 8 + q * 2;
        if (rA < NN)
            *reinterpret_cast<__half2*>(&g_h1h[(size_t)rA * HID + col]) =
                __floats2half2_rn(acc[nt][0], acc[nt][1]);
        if (rB < NN)
            *reinterpret_cast<__half2*>(&g_h1h[(size_t)rB * HID + col]) =
                __floats2half2_rn(acc[nt][2], acc[nt][3]);
    }
}

// ---------------- fused: layer-1 aggregate + relu + GEMM2 -> h2 (fp16) --------
// warp per dst; W2 rows 2*lane, 2*lane+1 live in REGISTERS (no smem, no
// bank conflicts); class partials reduced via shfl butterfly.
__global__ void __launch_bounds__(256)
k_agg1g2(const float* __restrict__ b1, const float* __restrict__ W2) {
    int tid = threadIdx.x;
    int lane = tid & 31;

    // per-lane weight registers: rows 2*lane and 2*lane+1 of W2 [HID][NCLS]
    float w0[NCLS], w1[NCLS];
#pragma unroll
    for (int c4 = 0; c4 < NCLS / 4; c4++) {
        float4 a = *reinterpret_cast<const float4*>(&W2[(2 * lane) * NCLS + c4 * 4]);
        float4 b = *reinterpret_cast<const float4*>(&W2[(2 * lane + 1) * NCLS + c4 * 4]);
        w0[4 * c4 + 0] = a.x; w0[4 * c4 + 1] = a.y; w0[4 * c4 + 2] = a.z; w0[4 * c4 + 3] = a.w;
        w1[4 * c4 + 0] = b.x; w1[4 * c4 + 1] = b.y; w1[4 * c4 + 2] = b.z; w1[4 * c4 + 3] = b.w;
    }
    float2 bb = *reinterpret_cast<const float2*>(&b1[2 * lane]);

    int d = blockIdx.x * 8 + (tid >> 5);
    if (d >= NN) return;
    int start = g_off[d], n = g_count[d];

    __half2 hv = *reinterpret_cast<const __half2*>(&g_h1h[(size_t)d * HID + lane * 2]);
    float2 v0 = __half22float2(hv);
    float sl = g_selfnorm[d];
    float2 acc = make_float2(v0.x * sl, v0.y * sl);

    const int2* ep = g_edge + start;
    int j = 0;
    for (; j + 2 <= n; j += 2) {                 // 2-way unroll for MLP
        int2 e0 = ep[j], e1 = ep[j + 1];
        __half2 h0 = *reinterpret_cast<const __half2*>(&g_h1h[(size_t)e0.x * HID + lane * 2]);
        __half2 h1 = *reinterpret_cast<const __half2*>(&g_h1h[(size_t)e1.x * HID + lane * 2]);
        float n0 = __int_as_float(e0.y), n1 = __int_as_float(e1.y);
        float2 f0 = __half22float2(h0), f1 = __half22float2(h1);
        acc.x = fmaf(f0.x, n0, acc.x);
        acc.y = fmaf(f0.y, n0, acc.y);
        acc.x = fmaf(f1.x, n1, acc.x);
        acc.y = fmaf(f1.y, n1, acc.y);
    }
    if (j < n) {
        int2 e0 = ep[j];
        __half2 h0 = *reinterpret_cast<const __half2*>(&g_h1h[(size_t)e0.x * HID + lane * 2]);
        float n0 = __int_as_float(e0.y);
        float2 f0 = __half22float2(h0);
        acc.x = fmaf(f0.x, n0, acc.x);
        acc.y = fmaf(f0.y, n0, acc.y);
    }

    float zx = fmaxf(acc.x + bb.x, 0.0f);
    float zy = fmaxf(acc.y + bb.y, 0.0f);
    float p[NCLS];
#pragma unroll
    for (int c = 0; c < NCLS; c++)
        p[c] = fmaf(zx, w0[c], zy * w1[c]);      // registers only
#pragma unroll
    for (int m = 16; m; m >>= 1)
#pragma unroll
        for (int c = 0; c < NCLS; c++)
            p[c] += __shfl_xor_sync(0xFFFFFFFFu, p[c], m);

    if (lane < 8)
        *reinterpret_cast<__half2*>(&g_h2h[(size_t)d * NCLS + 2 * lane]) =
            __floats2half2_rn(p[2 * lane], p[2 * lane + 1]);
}

// ---------------- layer-2 aggregation + bias + log_softmax (fused) ------------
__global__ void __launch_bounds__(256)
k_agg2_sm(const float* __restrict__ b2, float* __restrict__ out) {
    int warp = blockIdx.x * 8 + (threadIdx.x >> 5);
    int lane = threadIdx.x & 31;
    int d = warp * 2 + (lane >> 4);
    int f = lane & 15;
    if (d >= NN) return;
    int start = g_off[d], n = g_count[d];
    float acc = __half2float(g_h2h[(size_t)d * NCLS + f]) * g_selfnorm[d];
    const int2* ep = g_edge + start;
    int j = 0;
    for (; j + 2 <= n; j += 2) {
        int2 e0 = ep[j], e1 = ep[j + 1];
        float v0 = __half2float(g_h2h[(size_t)e0.x * NCLS + f]);
        float v1 = __half2float(g_h2h[(size_t)e1.x * NCLS + f]);
        acc = fmaf(v0, __int_as_float(e0.y), acc);
        acc = fmaf(v1, __int_as_float(e1.y), acc);
    }
    if (j < n) {
        int2 e0 = ep[j];
        acc = fmaf(__half2float(g_h2h[(size_t)e0.x * NCLS + f]),
                   __int_as_float(e0.y), acc);
    }
    float v = acc + b2[f];
    float m = v;
#pragma unroll
    for (int msk = 8; msk; msk >>= 1) m = fmaxf(m, __shfl_xor_sync(0xFFFFFFFFu, m, msk));
    float s = expf(v - m);
#pragma unroll
    for (int msk = 8; msk; msk >>= 1) s += __shfl_xor_sync(0xFFFFFFFFu, s, msk);
    out[(size_t)d * NCLS + f] = v - (logf(s) + m);
}

// ---------------- launch ------------------------------------------------------
extern "C" void kernel_launch(void* const* d_in, const int* in_sizes, int n_in,
                              void* d_out, int out_size) {
    const float* x  = (const float*)d_in[0];
    const int*   ei = (const int*)  d_in[1];
    const float* ew = (const float*)d_in[2];
    const float* W1 = (const float*)d_in[3];
    const float* b1 = (const float*)d_in[4];
    const float* W2 = (const float*)d_in[5];
    const float* b2 = (const float*)d_in[6];
    float* out = (float*)d_out;

    const int* src = ei;
    const int* dst = ei + EE;

    k_zero     <<<(NN + 255) / 256, 256>>>();
    k_hist     <<<(EE + 255) / 256, 256>>>(dst, ew);
    k_dis      <<<(NN + 255) / 256, 256>>>();
    k_scan1    <<<NCH, 1024>>>();
    k_scan2    <<<1, 128>>>();
    k_scan3    <<<(NN + 255) / 256, 256>>>();
    k_fill     <<<(EE + 255) / 256, 256>>>(src, dst, ew);
    k_prep_w   <<<(HID * INDIM + 255) / 256, 256>>>(W1);

    k_gemm1_tc <<<(NN + 127) / 128, 256>>>(x);
    k_agg1g2   <<<(NN + 7) / 8, 256>>>(b1, W2);
    k_agg2_sm  <<<(NN / 2 + 7) / 8, 256>>>(b2, out);
}

// round 8
// speedup vs baseline: 1.8343x; 1.8343x over previous
#include <cuda_runtime.h>
#include <cuda_bf16.h>
#include <cuda_fp16.h>
#include <cstdint>

#define NN      100000
#define EE      1600000
#define INDIM   512
#define HID     64
#define NCLS    16
#define NCH     ((NN + 1023) / 1024)     // 98 scan chunks

// ---------------- scratch (static device globals; no allocation) -------------
__device__ float g_dis[NN];
__device__ float g_selfnorm[NN];
__device__ __half g_h1h[(size_t)NN * HID];   // fp16 h1  <-- the ONE change vs R5
__device__ float g_agg1[(size_t)NN * HID];
__device__ float g_h2[(size_t)NN * NCLS];
__device__ int   g_count[NN];
__device__ int   g_off[NN];
__device__ int   g_cursor[NN];
__device__ int   g_bsum[128];
__device__ int   g_bcarry[128];
__device__ int2  g_edge[EE];             // (src, w-bits) sorted by dst
__device__ __nv_bfloat16 g_w1t_hi[HID * INDIM];
__device__ __nv_bfloat16 g_w1t_lo[HID * INDIM];

// ---------------- helpers -----------------------------------------------------
__device__ __forceinline__ uint32_t packbf(float first, float second) {
    uint32_t r;
    asm("cvt.rn.bf16x2.f32 %0, %1, %2;" : "=r"(r) : "f"(second), "f"(first));
    return r;
}

__device__ __forceinline__ void mma_bf16(float& d0, float& d1, float& d2, float& d3,
                                         uint32_t a0, uint32_t a1, uint32_t a2, uint32_t a3,
                                         uint32_t b0, uint32_t b1) {
    asm volatile(
        "mma.sync.aligned.m16n8k16.row.col.f32.bf16.bf16.f32 "
        "{%0,%1,%2,%3}, {%4,%5,%6,%7}, {%8,%9}, {%0,%1,%2,%3};"
        : "+f"(d0), "+f"(d1), "+f"(d2), "+f"(d3)
        : "r"(a0), "r"(a1), "r"(a2), "r"(a3), "r"(b0), "r"(b1));
}

// ---------------- CSR build ---------------------------------------------------
__global__ void k_zero() {
    int i = blockIdx.x * blockDim.x + threadIdx.x;
    if (i < NN) g_count[i] = 0;
}

__global__ void k_hist(const int* __restrict__ dst) {
    int e = blockIdx.x * blockDim.x + threadIdx.x;
    if (e < EE) atomicAdd(&g_count[dst[e]], 1);
}

__global__ void k_scan1() {
    __shared__ int sm[1024];
    int tid = threadIdx.x;
    int i = blockIdx.x * 1024 + tid;
    int v = (i < NN) ? g_count[i] : 0;
    sm[tid] = v;
    __syncthreads();
#pragma unroll
    for (int off = 1; off < 1024; off <<= 1) {
        int t = (tid >= off) ? sm[tid - off] : 0;
        __syncthreads();
        sm[tid] += t;
        __syncthreads();
    }
    if (i < NN) g_off[i] = sm[tid] - v;
    if (tid == 1023) g_bsum[blockIdx.x] = sm[tid];
}

__global__ void k_scan2() {
    __shared__ int sm[128];
    int tid = threadIdx.x;
    int v = (tid < NCH) ? g_bsum[tid] : 0;
    sm[tid] = v;
    __syncthreads();
#pragma unroll
    for (int off = 1; off < 128; off <<= 1) {
        int t = (tid >= off) ? sm[tid - off] : 0;
        __syncthreads();
        sm[tid] += t;
        __syncthreads();
    }
    g_bcarry[tid] = sm[tid] - v;
}

__global__ void k_scan3() {
    int i = blockIdx.x * blockDim.x + threadIdx.x;
    if (i < NN) {
        int o = g_off[i] + g_bcarry[i >> 10];
        g_off[i] = o;
        g_cursor[i] = o;
    }
}

__global__ void k_fill(const int* __restrict__ src, const int* __restrict__ dst,
                       const float* __restrict__ ew) {
    int e = blockIdx.x * blockDim.x + threadIdx.x;
    if (e >= EE) return;
    int d = dst[e];
    int pos = atomicAdd(&g_cursor[d], 1);
    g_edge[pos] = make_int2(src[e], __float_as_int(ew[e]));
}

// warp per dst: deg = 1 + sum(w); dis = rsqrt(deg); selfnorm = dis^2
__global__ void k_deg_csr() {
    int d = blockIdx.x * 8 + (threadIdx.x >> 5);
    if (d >= NN) return;
    int lane = threadIdx.x & 31;
    int start = g_off[d], n = g_count[d];
    float s = 0.f;
    for (int j = lane; j < n; j += 32) s += __int_as_float(g_edge[start + j].y);
#pragma unroll
    for (int m = 16; m; m >>= 1) s += __shfl_xor_sync(0xFFFFFFFFu, s, m);
    if (lane == 0) {
        float r = rsqrtf(s + 1.0f);
        g_dis[d] = r;
        g_selfnorm[d] = r * r;
    }
}

// fold dis[src] into stored edge weight: edge.y = w * dis[src]
__global__ void k_prenorm() {
    int j = blockIdx.x * blockDim.x + threadIdx.x;
    if (j >= EE) return;
    int2 ed = g_edge[j];
    g_edge[j].y = __float_as_int(__int_as_float(ed.y) * g_dis[ed.x]);
}

// ---------------- W1^T split prep ---------------------------------------------
__global__ void k_prep_w(const float* __restrict__ W1) {
    int idx = blockIdx.x * blockDim.x + threadIdx.x;
    if (idx >= HID * INDIM) return;
    int n = idx >> 9;
    int k = idx & 511;
    float w = W1[k * HID + n];
    __nv_bfloat16 h = __float2bfloat16_rn(w);
    float hf = __bfloat162float(h);
    g_w1t_hi[n * INDIM + k] = h;
    g_w1t_lo[n * INDIM + k] = __float2bfloat16_rn(w - hf);
}

// ---------------- GEMM1 via mma.sync split-bf16 -> h1 (fp16) ------------------
#define KC     32
#define APITCH 40
#define APB    (APITCH * 2)

__global__ void __launch_bounds__(256)
k_gemm1_tc(const float* __restrict__ x) {
    __shared__ uint8_t As_hi[128 * APB];
    __shared__ uint8_t As_lo[128 * APB];
    __shared__ uint8_t Bs_hi[64 * APB];
    __shared__ uint8_t Bs_lo[64 * APB];

    int tid = threadIdx.x;
    int wid = tid >> 5;
    int lane = tid & 31;
    int lt = lane >> 2;
    int q  = lane & 3;
    int row0 = blockIdx.x * 128;

    float acc[8][4];
#pragma unroll
    for (int t = 0; t < 8; t++)
#pragma unroll
        for (int j = 0; j < 4; j++) acc[t][j] = 0.0f;

    const uint2* whi = reinterpret_cast<const uint2*>(g_w1t_hi);
    const uint2* wlo = reinterpret_cast<const uint2*>(g_w1t_lo);

    for (int k0 = 0; k0 < INDIM; k0 += KC) {
#pragma unroll
        for (int i = 0; i < 4; i++) {
            int idx = tid + i * 256;
            int r = idx >> 3;
            int c4 = (idx & 7) * 4;
            float4 v = make_float4(0.f, 0.f, 0.f, 0.f);
            int grow = row0 + r;
            if (grow < NN)
                v = *reinterpret_cast<const float4*>(&x[(size_t)grow * INDIM + k0 + c4]);
            uint32_t hp0 = packbf(v.x, v.y);
            uint32_t hp1 = packbf(v.z, v.w);
            float hx = __uint_as_float(hp0 << 16);
            float hy = __uint_as_float(hp0 & 0xFFFF0000u);
            float hz = __uint_as_float(hp1 << 16);
            float hw = __uint_as_float(hp1 & 0xFFFF0000u);
            uint32_t lp0 = packbf(v.x - hx, v.y - hy);
            uint32_t lp1 = packbf(v.z - hz, v.w - hw);
            uint32_t off = (uint32_t)(r * APB + c4 * 2);
            *reinterpret_cast<uint2*>(As_hi + off) = make_uint2(hp0, hp1);
            *reinterpret_cast<uint2*>(As_lo + off) = make_uint2(lp0, lp1);
        }
#pragma unroll
        for (int i = 0; i < 2; i++) {
            int idx = tid + i * 256;
            int n = idx >> 3;
            int j = idx & 7;
            int gidx = n * 128 + (k0 >> 2) + j;
            uint32_t off = (uint32_t)(n * APB + j * 8);
            *reinterpret_cast<uint2*>(Bs_hi + off) = whi[gidx];
            *reinterpret_cast<uint2*>(Bs_lo + off) = wlo[gidx];
        }
        __syncthreads();

#pragma unroll
        for (int ks = 0; ks < 2; ks++) {
            uint32_t abase = (uint32_t)((wid * 16 + lt) * APB + ks * 32 + q * 4);
            uint32_t ah0 = *reinterpret_cast<const uint32_t*>(As_hi + abase);
            uint32_t ah1 = *reinterpret_cast<const uint32_t*>(As_hi + abase + 8 * APB);
            uint32_t ah2 = *reinterpret_cast<const uint32_t*>(As_hi + abase + 16);
            uint32_t ah3 = *reinterpret_cast<const uint32_t*>(As_hi + abase + 8 * APB + 16);
            uint32_t al0 = *reinterpret_cast<const uint32_t*>(As_lo + abase);
            uint32_t al1 = *reinterpret_cast<const uint32_t*>(As_lo + abase + 8 * APB);
            uint32_t al2 = *reinterpret_cast<const uint32_t*>(As_lo + abase + 16);
            uint32_t al3 = *reinterpret_cast<const uint32_t*>(As_lo + abase + 8 * APB + 16);
#pragma unroll
            for (int nt = 0; nt < 8; nt++) {
                uint32_t bbase = (uint32_t)((nt * 8 + lt) * APB + ks * 32 + q * 4);
                uint32_t bh0 = *reinterpret_cast<const uint32_t*>(Bs_hi + bbase);
                uint32_t bh1 = *reinterpret_cast<const uint32_t*>(Bs_hi + bbase + 16);
                uint32_t bl0 = *reinterpret_cast<const uint32_t*>(Bs_lo + bbase);
                uint32_t bl1 = *reinterpret_cast<const uint32_t*>(Bs_lo + bbase + 16);
                mma_bf16(acc[nt][0], acc[nt][1], acc[nt][2], acc[nt][3],
                         ah0, ah1, ah2, ah3, bh0, bh1);
                mma_bf16(acc[nt][0], acc[nt][1], acc[nt][2], acc[nt][3],
                         ah0, ah1, ah2, ah3, bl0, bl1);
                mma_bf16(acc[nt][0], acc[nt][1], acc[nt][2], acc[nt][3],
                         al0, al1, al2, al3, bh0, bh1);
            }
        }
        __syncthreads();
    }

    int rA = row0 + wid * 16 + lt;
    int rB = rA + 8;
#pragma unroll
    for (int nt = 0; nt < 8; nt++) {
        int col = nt * 8 + q * 2;
        if (rA < NN)
            *reinterpret_cast<__half2*>(&g_h1h[(size_t)rA * HID + col]) =
                __floats2half2_rn(acc[nt][0], acc[nt][1]);
        if (rB < NN)
            *reinterpret_cast<__half2*>(&g_h1h[(size_t)rB * HID + col]) =
                __floats2half2_rn(acc[nt][2], acc[nt][3]);
    }
}

// ---------------- layer-1 aggregation: warp per dst, gather-reduce ------------
__global__ void __launch_bounds__(256)
k_agg1() {
    int d = blockIdx.x * 8 + (threadIdx.x >> 5);
    if (d >= NN) return;
    int lane = threadIdx.x & 31;
    int start = g_off[d], n = g_count[d];
    float dd = g_dis[d];
    float sl = g_selfnorm[d];
    __half2 hv = *reinterpret_cast<const __half2*>(&g_h1h[(size_t)d * HID + lane * 2]);
    float2 v0 = __half22float2(hv);
    float2 acc = make_float2(v0.x * sl, v0.y * sl);
    const int2* ep = g_edge + start;
    for (int j = 0; j < n; j++) {
        int2 ed = ep[j];
        float nm = __int_as_float(ed.y) * dd;
        __half2 h = *reinterpret_cast<const __half2*>(&g_h1h[(size_t)ed.x * HID + lane * 2]);
        float2 v = __half22float2(h);
        acc.x = fmaf(v.x, nm, acc.x);
        acc.y = fmaf(v.y, nm, acc.y);
    }
    *reinterpret_cast<float2*>(&g_agg1[(size_t)d * HID + lane * 2]) = acc;
}

// ---------------- GEMM2: relu(agg1+b1) @ W2 -> h2 ----------------------------
__global__ void k_gemm2(const float* __restrict__ b1, const float* __restrict__ W2) {
    __shared__ float w2s[HID * NCLS];
    __shared__ float b1s[HID];
    int tid = threadIdx.x;
    for (int i = tid; i < HID * NCLS; i += blockDim.x) w2s[i] = W2[i];
    if (tid < HID) b1s[tid] = b1[tid];
    __syncthreads();
    int row = blockIdx.x * blockDim.x + tid;
    if (row >= NN) return;
    float acc[NCLS];
#pragma unroll
    for (int c = 0; c < NCLS; c++) acc[c] = 0.0f;
    const float4* arow = reinterpret_cast<const float4*>(&g_agg1[(size_t)row * HID]);
#pragma unroll
    for (int k4 = 0; k4 < HID / 4; k4++) {
        float4 v = arow[k4];
        float z0 = fmaxf(v.x + b1s[4 * k4 + 0], 0.0f);
        float z1 = fmaxf(v.y + b1s[4 * k4 + 1], 0.0f);
        float z2 = fmaxf(v.z + b1s[4 * k4 + 2], 0.0f);
        float z3 = fmaxf(v.w + b1s[4 * k4 + 3], 0.0f);
#pragma unroll
        for (int c = 0; c < NCLS; c++) {
            acc[c] = fmaf(z0, w2s[(4 * k4 + 0) * NCLS + c], acc[c]);
            acc[c] = fmaf(z1, w2s[(4 * k4 + 1) * NCLS + c], acc[c]);
            acc[c] = fmaf(z2, w2s[(4 * k4 + 2) * NCLS + c], acc[c]);
            acc[c] = fmaf(z3, w2s[(4 * k4 + 3) * NCLS + c], acc[c]);
        }
    }
#pragma unroll
    for (int c = 0; c < NCLS; c++) g_h2[(size_t)row * NCLS + c] = acc[c];
}

// ---------------- layer-2 aggregation + bias + log_softmax (fused) ------------
__global__ void __launch_bounds__(256)
k_agg2_sm(const float* __restrict__ b2, float* __restrict__ out) {
    int warp = blockIdx.x * 8 + (threadIdx.x >> 5);
    int lane = threadIdx.x & 31;
    int d = warp * 2 + (lane >> 4);
    int f = lane & 15;
    if (d >= NN) return;
    int start = g_off[d], n = g_count[d];
    float dd = g_dis[d];
    float acc = g_h2[(size_t)d * NCLS + f] * g_selfnorm[d];
    const int2* ep = g_edge + start;
    for (int j = 0; j < n; j++) {
        int2 ed = ep[j];
        float nm = __int_as_float(ed.y) * dd;
        acc = fmaf(g_h2[(size_t)ed.x * NCLS + f], nm, acc);
    }
    float v = acc + b2[f];
    float m = v;
#pragma unroll
    for (int msk = 8; msk; msk >>= 1) m = fmaxf(m, __shfl_xor_sync(0xFFFFFFFFu, m, msk));
    float s = expf(v - m);
#pragma unroll
    for (int msk = 8; msk; msk >>= 1) s += __shfl_xor_sync(0xFFFFFFFFu, s, msk);
    out[(size_t)d * NCLS + f] = v - (logf(s) + m);
}

// ---------------- launch ------------------------------------------------------
extern "C" void kernel_launch(void* const* d_in, const int* in_sizes, int n_in,
                              void* d_out, int out_size) {
    const float* x  = (const float*)d_in[0];
    const int*   ei = (const int*)  d_in[1];
    const float* ew = (const float*)d_in[2];
    const float* W1 = (const float*)d_in[3];
    const float* b1 = (const float*)d_in[4];
    const float* W2 = (const float*)d_in[5];
    const float* b2 = (const float*)d_in[6];
    float* out = (float*)d_out;

    const int* src = ei;
    const int* dst = ei + EE;

    k_zero     <<<(NN + 255) / 256, 256>>>();
    k_hist     <<<(EE + 255) / 256, 256>>>(dst);
    k_scan1    <<<NCH, 1024>>>();
    k_scan2    <<<1, 128>>>();
    k_scan3    <<<(NN + 255) / 256, 256>>>();
    k_fill     <<<(EE + 255) / 256, 256>>>(src, dst, ew);
    k_deg_csr  <<<(NN + 7) / 8, 256>>>();
    k_prenorm  <<<(EE + 255) / 256, 256>>>();
    k_prep_w   <<<(HID * INDIM + 255) / 256, 256>>>(W1);

    k_gemm1_tc <<<(NN + 127) / 128, 256>>>(x);
    k_agg1     <<<(NN + 7) / 8, 256>>>();
    k_gemm2    <<<(NN + 255) / 256, 256>>>(b1, W2);
    k_agg2_sm  <<<(NN / 2 + 7) / 8, 256>>>(b2, out);
}

// round 10
// speedup vs baseline: 2.1172x; 1.1543x over previous
#include <cuda_runtime.h>
#include <cuda_bf16.h>
#include <cuda_fp16.h>
#include <cstdint>

#define NN      100000
#define EE      1600000
#define INDIM   512
#define HID     64
#define NCLS    16
#define NCH     ((NN + 1023) / 1024)     // 98 scan chunks

// ---------------- scratch (static device globals; no allocation) -------------
__device__ float g_dis[NN];
__device__ float g_selfnorm[NN];
__device__ __half g_h1h[(size_t)NN * HID];
__device__ float g_agg1[(size_t)NN * HID];
__device__ float g_h2[(size_t)NN * NCLS];
__device__ int   g_count[NN];
__device__ int   g_off[NN];
__device__ int   g_cursor[NN];
__device__ int   g_bsum[128];
__device__ int   g_bcarry[128];
__device__ int2  g_edge[EE];             // (src, w-bits) sorted by dst
__device__ __nv_bfloat16 g_w1t_hi[HID * INDIM];
__device__ __nv_bfloat16 g_w1t_lo[HID * INDIM];

// ---------------- helpers -----------------------------------------------------
__device__ __forceinline__ uint32_t packbf(float first, float second) {
    uint32_t r;
    asm("cvt.rn.bf16x2.f32 %0, %1, %2;" : "=r"(r) : "f"(second), "f"(first));
    return r;
}

__device__ __forceinline__ void mma_bf16(float& d0, float& d1, float& d2, float& d3,
                                         uint32_t a0, uint32_t a1, uint32_t a2, uint32_t a3,
                                         uint32_t b0, uint32_t b1) {
    asm volatile(
        "mma.sync.aligned.m16n8k16.row.col.f32.bf16.bf16.f32 "
        "{%0,%1,%2,%3}, {%4,%5,%6,%7}, {%8,%9}, {%0,%1,%2,%3};"
        : "+f"(d0), "+f"(d1), "+f"(d2), "+f"(d3)
        : "r"(a0), "r"(a1), "r"(a2), "r"(a3), "r"(b0), "r"(b1));
}

// ---------------- CSR build ---------------------------------------------------
__global__ void k_zero() {
    int i = blockIdx.x * blockDim.x + threadIdx.x;
    if (i < NN) g_count[i] = 0;
}

__global__ void k_hist(const int* __restrict__ dst) {
    int e = blockIdx.x * blockDim.x + threadIdx.x;
    if (e < EE) atomicAdd(&g_count[dst[e]], 1);
}

__global__ void k_scan1() {
    __shared__ int sm[1024];
    int tid = threadIdx.x;
    int i = blockIdx.x * 1024 + tid;
    int v = (i < NN) ? g_count[i] : 0;
    sm[tid] = v;
    __syncthreads();
#pragma unroll
    for (int off = 1; off < 1024; off <<= 1) {
        int t = (tid >= off) ? sm[tid - off] : 0;
        __syncthreads();
        sm[tid] += t;
        __syncthreads();
    }
    if (i < NN) g_off[i] = sm[tid] - v;
    if (tid == 1023) g_bsum[blockIdx.x] = sm[tid];
}

__global__ void k_scan2() {
    __shared__ int sm[128];
    int tid = threadIdx.x;
    int v = (tid < NCH) ? g_bsum[tid] : 0;
    sm[tid] = v;
    __syncthreads();
#pragma unroll
    for (int off = 1; off < 128; off <<= 1) {
        int t = (tid >= off) ? sm[tid - off] : 0;
        __syncthreads();
        sm[tid] += t;
        __syncthreads();
    }
    g_bcarry[tid] = sm[tid] - v;
}

__global__ void k_scan3() {
    int i = blockIdx.x * blockDim.x + threadIdx.x;
    if (i < NN) {
        int o = g_off[i] + g_bcarry[i >> 10];
        g_off[i] = o;
        g_cursor[i] = o;
    }
}

__global__ void k_fill(const int* __restrict__ src, const int* __restrict__ dst,
                       const float* __restrict__ ew) {
    int e = blockIdx.x * blockDim.x + threadIdx.x;
    if (e >= EE) return;
    int d = dst[e];
    int pos = atomicAdd(&g_cursor[d], 1);
    g_edge[pos] = make_int2(src[e], __float_as_int(ew[e]));
}

// warp per dst: deg = 1 + sum(w); dis = rsqrt(deg); selfnorm = dis^2
__global__ void k_deg_csr() {
    int d = blockIdx.x * 8 + (threadIdx.x >> 5);
    if (d >= NN) return;
    int lane = threadIdx.x & 31;
    int start = g_off[d], n = g_count[d];
    float s = 0.f;
    for (int j = lane; j < n; j += 32) s += __int_as_float(g_edge[start + j].y);
#pragma unroll
    for (int m = 16; m; m >>= 1) s += __shfl_xor_sync(0xFFFFFFFFu, s, m);
    if (lane == 0) {
        float r = rsqrtf(s + 1.0f);
        g_dis[d] = r;
        g_selfnorm[d] = r * r;
    }
}

// fold dis[src] into stored edge weight: edge.y = w * dis[src]
__global__ void k_prenorm() {
    int j = blockIdx.x * blockDim.x + threadIdx.x;
    if (j >= EE) return;
    int2 ed = g_edge[j];
    g_edge[j].y = __float_as_int(__int_as_float(ed.y) * g_dis[ed.x]);
}

// ---------------- W1^T split prep ---------------------------------------------
__global__ void k_prep_w(const float* __restrict__ W1) {
    int idx = blockIdx.x * blockDim.x + threadIdx.x;
    if (idx >= HID * INDIM) return;
    int n = idx >> 9;
    int k = idx & 511;
    float w = W1[k * HID + n];
    __nv_bfloat16 h = __float2bfloat16_rn(w);
    float hf = __bfloat162float(h);
    g_w1t_hi[n * INDIM + k] = h;
    g_w1t_lo[n * INDIM + k] = __float2bfloat16_rn(w - hf);
}

// ---------------- GEMM1: split-bf16 mma.sync, register-prefetch pipeline ------
#define KC     32
#define APITCH 40
#define APB    (APITCH * 2)

__global__ void __launch_bounds__(256)
k_gemm1_tc(const float* __restrict__ x) {
    __shared__ uint8_t As_hi[128 * APB];
    __shared__ uint8_t As_lo[128 * APB];
    __shared__ uint8_t Bs_hi[64 * APB];
    __shared__ uint8_t Bs_lo[64 * APB];

    int tid = threadIdx.x;
    int wid = tid >> 5;
    int lane = tid & 31;
    int lt = lane >> 2;
    int q  = lane & 3;
    int row0 = blockIdx.x * 128;

    float acc[8][4];
#pragma unroll
    for (int t = 0; t < 8; t++)
#pragma unroll
        for (int j = 0; j < 4; j++) acc[t][j] = 0.0f;

    const uint2* whi = reinterpret_cast<const uint2*>(g_w1t_hi);
    const uint2* wlo = reinterpret_cast<const uint2*>(g_w1t_lo);

    // register staging for the prefetch pipeline
    float4 vx[4];
    uint2  vbh[2], vbl[2];

    auto load_g = [&](int k0) {
#pragma unroll
        for (int i = 0; i < 4; i++) {
            int idx = tid + i * 256;
            int r = idx >> 3;
            int c4 = (idx & 7) * 4;
            int grow = row0 + r;
            vx[i] = (grow < NN)
                ? *reinterpret_cast<const float4*>(&x[(size_t)grow * INDIM + k0 + c4])
                : make_float4(0.f, 0.f, 0.f, 0.f);
        }
#pragma unroll
        for (int i = 0; i < 2; i++) {
            int idx = tid + i * 256;
            int n = idx >> 3;
            int j = idx & 7;
            int gidx = n * 128 + (k0 >> 2) + j;
            vbh[i] = whi[gidx];
            vbl[i] = wlo[gidx];
        }
    };

    auto store_s = [&]() {
#pragma unroll
        for (int i = 0; i < 4; i++) {
            int idx = tid + i * 256;
            int r = idx >> 3;
            int c4 = (idx & 7) * 4;
            float4 v = vx[i];
            uint32_t hp0 = packbf(v.x, v.y);
            uint32_t hp1 = packbf(v.z, v.w);
            float hx = __uint_as_float(hp0 << 16);
            float hy = __uint_as_float(hp0 & 0xFFFF0000u);
            float hz = __uint_as_float(hp1 << 16);
            float hw = __uint_as_float(hp1 & 0xFFFF0000u);
            uint32_t lp0 = packbf(v.x - hx, v.y - hy);
            uint32_t lp1 = packbf(v.z - hz, v.w - hw);
            uint32_t off = (uint32_t)(r * APB + c4 * 2);
            *reinterpret_cast<uint2*>(As_hi + off) = make_uint2(hp0, hp1);
            *reinterpret_cast<uint2*>(As_lo + off) = make_uint2(lp0, lp1);
        }
#pragma unroll
        for (int i = 0; i < 2; i++) {
            int idx = tid + i * 256;
            int n = idx >> 3;
            int j = idx & 7;
            uint32_t off = (uint32_t)(n * APB + j * 8);
            *reinterpret_cast<uint2*>(Bs_hi + off) = vbh[i];
            *reinterpret_cast<uint2*>(Bs_lo + off) = vbl[i];
        }
    };

    load_g(0);
    store_s();
    __syncthreads();

    for (int c = 0; c < INDIM / KC; c++) {
        bool more = (c + 1 < INDIM / KC);
        if (more) load_g((c + 1) * KC);      // LDG issued early, overlaps MMA

#pragma unroll
        for (int ks = 0; ks < 2; ks++) {
            uint32_t abase = (uint32_t)((wid * 16 + lt) * APB + ks * 32 + q * 4);
            uint32_t ah0 = *reinterpret_cast<const uint32_t*>(As_hi + abase);
            uint32_t ah1 = *reinterpret_cast<const uint32_t*>(As_hi + abase + 8 * APB);
            uint32_t ah2 = *reinterpret_cast<const uint32_t*>(As_hi + abase + 16);
            uint32_t ah3 = *reinterpret_cast<const uint32_t*>(As_hi + abase + 8 * APB + 16);
            uint32_t al0 = *reinterpret_cast<const uint32_t*>(As_lo + abase);
            uint32_t al1 = *reinterpret_cast<const uint32_t*>(As_lo + abase + 8 * APB);
            uint32_t al2 = *reinterpret_cast<const uint32_t*>(As_lo + abase + 16);
            uint32_t al3 = *reinterpret_cast<const uint32_t*>(As_lo + abase + 8 * APB + 16);
#pragma unroll
            for (int nt = 0; nt < 8; nt++) {
                uint32_t bbase = (uint32_t)((nt * 8 + lt) * APB + ks * 32 + q * 4);
                uint32_t bh0 = *reinterpret_cast<const uint32_t*>(Bs_hi + bbase);
                uint32_t bh1 = *reinterpret_cast<const uint32_t*>(Bs_hi + bbase + 16);
                uint32_t bl0 = *reinterpret_cast<const uint32_t*>(Bs_lo + bbase);
                uint32_t bl1 = *reinterpret_cast<const uint32_t*>(Bs_lo + bbase + 16);
                mma_bf16(acc[nt][0], acc[nt][1], acc[nt][2], acc[nt][3],
                         ah0, ah1, ah2, ah3, bh0, bh1);
                mma_bf16(acc[nt][0], acc[nt][1], acc[nt][2], acc[nt][3],
                         ah0, ah1, ah2, ah3, bl0, bl1);
                mma_bf16(acc[nt][0], acc[nt][1], acc[nt][2], acc[nt][3],
                         al0, al1, al2, al3, bh0, bh1);
            }
        }
        __syncthreads();                      // all warps done reading tile c
        if (more) {
            store_s();                        // overwrite with tile c+1
            __syncthreads();
        }
    }

    int rA = row0 + wid * 16 + lt;
    int rB = rA + 8;
#pragma unroll
    for (int nt = 0; nt < 8; nt++) {
        int col = nt * 8 + q * 2;
        if (rA < NN)
            *reinterpret_cast<__half2*>(&g_h1h[(size_t)rA * HID + col]) =
                __floats2half2_rn(acc[nt][0], acc[nt][1]);
        if (rB < NN)
            *reinterpret_cast<__half2*>(&g_h1h[(size_t)rB * HID + col]) =
                __floats2half2_rn(acc[nt][2], acc[nt][3]);
    }
}

// ---------------- layer-1 aggregation: warp per dst, 4-edge unrolled ----------
__global__ void __launch_bounds__(256)
k_agg1() {
    int d = blockIdx.x * 8 + (threadIdx.x >> 5);
    if (d >= NN) return;
    int lane = threadIdx.x & 31;
    int start = g_off[d], n = g_count[d];
    float dd = g_dis[d];
    float sl = g_selfnorm[d];
    __half2 hv = *reinterpret_cast<const __half2*>(&g_h1h[(size_t)d * HID + lane * 2]);
    float2 v0 = __half22float2(hv);
    float2 acc = make_float2(v0.x * sl, v0.y * sl);
    const int2* ep = g_edge + start;
    int j = 0;
    for (; j + 4 <= n; j += 4) {
        int2 e0 = ep[j], e1 = ep[j + 1], e2 = ep[j + 2], e3 = ep[j + 3];
        __half2 h0 = *reinterpret_cast<const __half2*>(&g_h1h[(size_t)e0.x * HID + lane * 2]);
        __half2 h1 = *reinterpret_cast<const __half2*>(&g_h1h[(size_t)e1.x * HID + lane * 2]);
        __half2 h2 = *reinterpret_cast<const __half2*>(&g_h1h[(size_t)e2.x * HID + lane * 2]);
        __half2 h3 = *reinterpret_cast<const __half2*>(&g_h1h[(size_t)e3.x * HID + lane * 2]);
        float n0 = __int_as_float(e0.y) * dd, n1 = __int_as_float(e1.y) * dd;
        float n2 = __int_as_float(e2.y) * dd, n3 = __int_as_float(e3.y) * dd;
        float2 f0 = __half22float2(h0), f1 = __half22float2(h1);
        float2 f2 = __half22float2(h2), f3 = __half22float2(h3);
        acc.x = fmaf(f0.x, n0, acc.x); acc.y = fmaf(f0.y, n0, acc.y);
        acc.x = fmaf(f1.x, n1, acc.x); acc.y = fmaf(f1.y, n1, acc.y);
        acc.x = fmaf(f2.x, n2, acc.x); acc.y = fmaf(f2.y, n2, acc.y);
        acc.x = fmaf(f3.x, n3, acc.x); acc.y = fmaf(f3.y, n3, acc.y);
    }
    for (; j < n; j++) {
        int2 ed = ep[j];
        float nm = __int_as_float(ed.y) * dd;
        __half2 h = *reinterpret_cast<const __half2*>(&g_h1h[(size_t)ed.x * HID + lane * 2]);
        float2 v = __half22float2(h);
        acc.x = fmaf(v.x, nm, acc.x);
        acc.y = fmaf(v.y, nm, acc.y);
    }
    *reinterpret_cast<float2*>(&g_agg1[(size_t)d * HID + lane * 2]) = acc;
}

// ---------------- GEMM2: relu(agg1+b1) @ W2 -> h2 ----------------------------
__global__ void k_gemm2(const float* __restrict__ b1, const float* __restrict__ W2) {
    __shared__ float w2s[HID * NCLS];
    __shared__ float b1s[HID];
    int tid = threadIdx.x;
    for (int i = tid; i < HID * NCLS; i += blockDim.x) w2s[i] = W2[i];
    if (tid < HID) b1s[tid] = b1[tid];
    __syncthreads();
    int row = blockIdx.x * blockDim.x + tid;
    if (row >= NN) return;
    float acc[NCLS];
#pragma unroll
    for (int c = 0; c < NCLS; c++) acc[c] = 0.0f;
    const float4* arow = reinterpret_cast<const float4*>(&g_agg1[(size_t)row * HID]);
#pragma unroll
    for (int k4 = 0; k4 < HID / 4; k4++) {
        float4 v = arow[k4];
        float z0 = fmaxf(v.x + b1s[4 * k4 + 0], 0.0f);
        float z1 = fmaxf(v.y + b1s[4 * k4 + 1], 0.0f);
        float z2 = fmaxf(v.z + b1s[4 * k4 + 2], 0.0f);
        float z3 = fmaxf(v.w + b1s[4 * k4 + 3], 0.0f);
#pragma unroll
        for (int c = 0; c < NCLS; c++) {
            acc[c] = fmaf(z0, w2s[(4 * k4 + 0) * NCLS + c], acc[c]);
            acc[c] = fmaf(z1, w2s[(4 * k4 + 1) * NCLS + c], acc[c]);
            acc[c] = fmaf(z2, w2s[(4 * k4 + 2) * NCLS + c], acc[c]);
            acc[c] = fmaf(z3, w2s[(4 * k4 + 3) * NCLS + c], acc[c]);
        }
    }
#pragma unroll
    for (int c = 0; c < NCLS; c++) g_h2[(size_t)row * NCLS + c] = acc[c];
}

// ---------------- layer-2 aggregation + bias + log_softmax (fused) ------------
__global__ void __launch_bounds__(256)
k_agg2_sm(const float* __restrict__ b2, float* __restrict__ out) {
    int warp = blockIdx.x * 8 + (threadIdx.x >> 5);
    int lane = threadIdx.x & 31;
    int d = warp * 2 + (lane >> 4);
    int f = lane & 15;
    if (d >= NN) return;
    int start = g_off[d], n = g_count[d];
    float dd = g_dis[d];
    float acc = g_h2[(size_t)d * NCLS + f] * g_selfnorm[d];
    const int2* ep = g_edge + start;
    int j = 0;
    for (; j + 4 <= n; j += 4) {
        int2 e0 = ep[j], e1 = ep[j + 1], e2 = ep[j + 2], e3 = ep[j + 3];
        float v0 = g_h2[(size_t)e0.x * NCLS + f];
        float v1 = g_h2[(size_t)e1.x * NCLS + f];
        float v2 = g_h2[(size_t)e2.x * NCLS + f];
        float v3 = g_h2[(size_t)e3.x * NCLS + f];
        acc = fmaf(v0, __int_as_float(e0.y) * dd, acc);
        acc = fmaf(v1, __int_as_float(e1.y) * dd, acc);
        acc = fmaf(v2, __int_as_float(e2.y) * dd, acc);
        acc = fmaf(v3, __int_as_float(e3.y) * dd, acc);
    }
    for (; j < n; j++) {
        int2 ed = ep[j];
        float nm = __int_as_float(ed.y) * dd;
        acc = fmaf(g_h2[(size_t)ed.x * NCLS + f], nm, acc);
    }
    float v = acc + b2[f];
    float m = v;
#pragma unroll
    for (int msk = 8; msk; msk >>= 1) m = fmaxf(m, __shfl_xor_sync(0xFFFFFFFFu, m, msk));
    float s = expf(v - m);
#pragma unroll
    for (int msk = 8; msk; msk >>= 1) s += __shfl_xor_sync(0xFFFFFFFFu, s, msk);
    out[(size_t)d * NCLS + f] = v - (logf(s) + m);
}

// ---------------- launch ------------------------------------------------------
extern "C" void kernel_launch(void* const* d_in, const int* in_sizes, int n_in,
                              void* d_out, int out_size) {
    const float* x  = (const float*)d_in[0];
    const int*   ei = (const int*)  d_in[1];
    const float* ew = (const float*)d_in[2];
    const float* W1 = (const float*)d_in[3];
    const float* b1 = (const float*)d_in[4];
    const float* W2 = (const float*)d_in[5];
    const float* b2 = (const float*)d_in[6];
    float* out = (float*)d_out;

    const int* src = ei;
    const int* dst = ei + EE;

    k_zero     <<<(NN + 255) / 256, 256>>>();
    k_hist     <<<(EE + 255) / 256, 256>>>(dst);
    k_scan1    <<<NCH, 1024>>>();
    k_scan2    <<<1, 128>>>();
    k_scan3    <<<(NN + 255) / 256, 256>>>();
    k_fill     <<<(EE + 255) / 256, 256>>>(src, dst, ew);
    k_deg_csr  <<<(NN + 7) / 8, 256>>>();
    k_prenorm  <<<(EE + 255) / 256, 256>>>();
    k_prep_w   <<<(HID * INDIM + 255) / 256, 256>>>(W1);

    k_gemm1_tc <<<(NN + 127) / 128, 256>>>(x);
    k_agg1     <<<(NN + 7) / 8, 256>>>();
    k_gemm2    <<<(NN + 255) / 256, 256>>>(b1, W2);
    k_agg2_sm  <<<(NN / 2 + 7) / 8, 256>>>(b2, out);
}

// round 11
// speedup vs baseline: 2.1928x; 1.0357x over previous
#include <cuda_runtime.h>
#include <cuda_bf16.h>
#include <cuda_fp16.h>
#include <cstdint>

#define NN      100000
#define EE      1600000
#define INDIM   512
#define HID     64
#define NCLS    16
#define NCH     ((NN + 1023) / 1024)     // 98 scan chunks

// ---------------- scratch (static device globals; no allocation) -------------
__device__ float g_deg[NN];
__device__ float g_dis[NN];
__device__ float g_selfnorm[NN];
__device__ __half g_h1h[(size_t)NN * HID];
__device__ float g_agg1[(size_t)NN * HID];
__device__ float g_h2[(size_t)NN * NCLS];
__device__ int   g_count[NN];
__device__ int   g_off[NN];
__device__ int   g_cursor[NN];
__device__ int   g_bsum[128];
__device__ int   g_bcarry[128];
__device__ int2  g_edge[EE];             // (src, full-norm bits) sorted by dst
__device__ __nv_bfloat16 g_w1t_hi[HID * INDIM];
__device__ __nv_bfloat16 g_w1t_lo[HID * INDIM];

// ---------------- helpers -----------------------------------------------------
__device__ __forceinline__ uint32_t packbf(float first, float second) {
    uint32_t r;
    asm("cvt.rn.bf16x2.f32 %0, %1, %2;" : "=r"(r) : "f"(second), "f"(first));
    return r;
}

__device__ __forceinline__ void mma_bf16(float& d0, float& d1, float& d2, float& d3,
                                         uint32_t a0, uint32_t a1, uint32_t a2, uint32_t a3,
                                         uint32_t b0, uint32_t b1) {
    asm volatile(
        "mma.sync.aligned.m16n8k16.row.col.f32.bf16.bf16.f32 "
        "{%0,%1,%2,%3}, {%4,%5,%6,%7}, {%8,%9}, {%0,%1,%2,%3};"
        : "+f"(d0), "+f"(d1), "+f"(d2), "+f"(d3)
        : "r"(a0), "r"(a1), "r"(a2), "r"(a3), "r"(b0), "r"(b1));
}

// ---------------- CSR build ---------------------------------------------------
__global__ void k_zero() {
    int i = blockIdx.x * blockDim.x + threadIdx.x;
    if (i < NN) { g_count[i] = 0; g_deg[i] = 1.0f; }   // self-loop weight
}

// fused: edge histogram + weighted degree
__global__ void k_hist(const int* __restrict__ dst, const float* __restrict__ ew) {
    int e = blockIdx.x * blockDim.x + threadIdx.x;
    if (e < EE) {
        int d = dst[e];
        atomicAdd(&g_count[d], 1);
        atomicAdd(&g_deg[d], ew[e]);
    }
}

__global__ void k_dis() {
    int i = blockIdx.x * blockDim.x + threadIdx.x;
    if (i < NN) {
        float r = rsqrtf(g_deg[i]);
        g_dis[i] = r;
        g_selfnorm[i] = r * r;
    }
}

__global__ void k_scan1() {
    __shared__ int sm[1024];
    int tid = threadIdx.x;
    int i = blockIdx.x * 1024 + tid;
    int v = (i < NN) ? g_count[i] : 0;
    sm[tid] = v;
    __syncthreads();
#pragma unroll
    for (int off = 1; off < 1024; off <<= 1) {
        int t = (tid >= off) ? sm[tid - off] : 0;
        __syncthreads();
        sm[tid] += t;
        __syncthreads();
    }
    if (i < NN) g_off[i] = sm[tid] - v;
    if (tid == 1023) g_bsum[blockIdx.x] = sm[tid];
}

__global__ void k_scan2() {
    __shared__ int sm[128];
    int tid = threadIdx.x;
    int v = (tid < NCH) ? g_bsum[tid] : 0;
    sm[tid] = v;
    __syncthreads();
#pragma unroll
    for (int off = 1; off < 128; off <<= 1) {
        int t = (tid >= off) ? sm[tid - off] : 0;
        __syncthreads();
        sm[tid] += t;
        __syncthreads();
    }
    g_bcarry[tid] = sm[tid] - v;
}

__global__ void k_scan3() {
    int i = blockIdx.x * blockDim.x + threadIdx.x;
    if (i < NN) {
        int o = g_off[i] + g_bcarry[i >> 10];
        g_off[i] = o;
        g_cursor[i] = o;
    }
}

// fill with FULL norm dis[src]*w*dis[dst] (dis ready; dst known here)
__global__ void k_fill(const int* __restrict__ src, const int* __restrict__ dst,
                       const float* __restrict__ ew) {
    int e = blockIdx.x * blockDim.x + threadIdx.x;
    if (e >= EE) return;
    int s = src[e], d = dst[e];
    int pos = atomicAdd(&g_cursor[d], 1);
    float nm = g_dis[s] * ew[e] * g_dis[d];
    g_edge[pos] = make_int2(s, __float_as_int(nm));
}

// ---------------- W1^T split prep ---------------------------------------------
__global__ void k_prep_w(const float* __restrict__ W1) {
    int idx = blockIdx.x * blockDim.x + threadIdx.x;
    if (idx >= HID * INDIM) return;
    int n = idx >> 9;
    int k = idx & 511;
    float w = W1[k * HID + n];
    __nv_bfloat16 h = __float2bfloat16_rn(w);
    float hf = __bfloat162float(h);
    g_w1t_hi[n * INDIM + k] = h;
    g_w1t_lo[n * INDIM + k] = __float2bfloat16_rn(w - hf);
}

// ---------------- GEMM1: split-bf16 mma.sync, register-prefetch pipeline ------
#define KC     32
#define APITCH 40
#define APB    (APITCH * 2)

__global__ void __launch_bounds__(256)
k_gemm1_tc(const float* __restrict__ x) {
    __shared__ uint8_t As_hi[128 * APB];
    __shared__ uint8_t As_lo[128 * APB];
    __shared__ uint8_t Bs_hi[64 * APB];
    __shared__ uint8_t Bs_lo[64 * APB];

    int tid = threadIdx.x;
    int wid = tid >> 5;
    int lane = tid & 31;
    int lt = lane >> 2;
    int q  = lane & 3;
    int row0 = blockIdx.x * 128;

    float acc[8][4];
#pragma unroll
    for (int t = 0; t < 8; t++)
#pragma unroll
        for (int j = 0; j < 4; j++) acc[t][j] = 0.0f;

    const uint2* whi = reinterpret_cast<const uint2*>(g_w1t_hi);
    const uint2* wlo = reinterpret_cast<const uint2*>(g_w1t_lo);

    float4 vx[4];
    uint2  vbh[2], vbl[2];

    auto load_g = [&](int k0) {
#pragma unroll
        for (int i = 0; i < 4; i++) {
            int idx = tid + i * 256;
            int r = idx >> 3;
            int c4 = (idx & 7) * 4;
            int grow = row0 + r;
            vx[i] = (grow < NN)
                ? *reinterpret_cast<const float4*>(&x[(size_t)grow * INDIM + k0 + c4])
                : make_float4(0.f, 0.f, 0.f, 0.f);
        }
#pragma unroll
        for (int i = 0; i < 2; i++) {
            int idx = tid + i * 256;
            int n = idx >> 3;
            int j = idx & 7;
            int gidx = n * 128 + (k0 >> 2) + j;
            vbh[i] = whi[gidx];
            vbl[i] = wlo[gidx];
        }
    };

    auto store_s = [&]() {
#pragma unroll
        for (int i = 0; i < 4; i++) {
            int idx = tid + i * 256;
            int r = idx >> 3;
            int c4 = (idx & 7) * 4;
            float4 v = vx[i];
            uint32_t hp0 = packbf(v.x, v.y);
            uint32_t hp1 = packbf(v.z, v.w);
            float hx = __uint_as_float(hp0 << 16);
            float hy = __uint_as_float(hp0 & 0xFFFF0000u);
            float hz = __uint_as_float(hp1 << 16);
            float hw = __uint_as_float(hp1 & 0xFFFF0000u);
            uint32_t lp0 = packbf(v.x - hx, v.y - hy);
            uint32_t lp1 = packbf(v.z - hz, v.w - hw);
            uint32_t off = (uint32_t)(r * APB + c4 * 2);
            *reinterpret_cast<uint2*>(As_hi + off) = make_uint2(hp0, hp1);
            *reinterpret_cast<uint2*>(As_lo + off) = make_uint2(lp0, lp1);
        }
#pragma unroll
        for (int i = 0; i < 2; i++) {
            int idx = tid + i * 256;
            int n = idx >> 3;
            int j = idx & 7;
            uint32_t off = (uint32_t)(n * APB + j * 8);
            *reinterpret_cast<uint2*>(Bs_hi + off) = vbh[i];
            *reinterpret_cast<uint2*>(Bs_lo + off) = vbl[i];
        }
    };

    load_g(0);
    store_s();
    __syncthreads();

    for (int c = 0; c < INDIM / KC; c++) {
        bool more = (c + 1 < INDIM / KC);
        if (more) load_g((c + 1) * KC);

#pragma unroll
        for (int ks = 0; ks < 2; ks++) {
            uint32_t abase = (uint32_t)((wid * 16 + lt) * APB + ks * 32 + q * 4);
            uint32_t ah0 = *reinterpret_cast<const uint32_t*>(As_hi + abase);
            uint32_t ah1 = *reinterpret_cast<const uint32_t*>(As_hi + abase + 8 * APB);
            uint32_t ah2 = *reinterpret_cast<const uint32_t*>(As_hi + abase + 16);
            uint32_t ah3 = *reinterpret_cast<const uint32_t*>(As_hi + abase + 8 * APB + 16);
            uint32_t al0 = *reinterpret_cast<const uint32_t*>(As_lo + abase);
            uint32_t al1 = *reinterpret_cast<const uint32_t*>(As_lo + abase + 8 * APB);
            uint32_t al2 = *reinterpret_cast<const uint32_t*>(As_lo + abase + 16);
            uint32_t al3 = *reinterpret_cast<const uint32_t*>(As_lo + abase + 8 * APB + 16);
#pragma unroll
            for (int nt = 0; nt < 8; nt++) {
                uint32_t bbase = (uint32_t)((nt * 8 + lt) * APB + ks * 32 + q * 4);
                uint32_t bh0 = *reinterpret_cast<const uint32_t*>(Bs_hi + bbase);
                uint32_t bh1 = *reinterpret_cast<const uint32_t*>(Bs_hi + bbase + 16);
                uint32_t bl0 = *reinterpret_cast<const uint32_t*>(Bs_lo + bbase);
                uint32_t bl1 = *reinterpret_cast<const uint32_t*>(Bs_lo + bbase + 16);
                mma_bf16(acc[nt][0], acc[nt][1], acc[nt][2], acc[nt][3],
                         ah0, ah1, ah2, ah3, bh0, bh1);
                mma_bf16(acc[nt][0], acc[nt][1], acc[nt][2], acc[nt][3],
                         ah0, ah1, ah2, ah3, bl0, bl1);
                mma_bf16(acc[nt][0], acc[nt][1], acc[nt][2], acc[nt][3],
                         al0, al1, al2, al3, bh0, bh1);
            }
        }
        __syncthreads();
        if (more) {
            store_s();
            __syncthreads();
        }
    }

    int rA = row0 + wid * 16 + lt;
    int rB = rA + 8;
#pragma unroll
    for (int nt = 0; nt < 8; nt++) {
        int col = nt * 8 + q * 2;
        if (rA < NN)
            *reinterpret_cast<__half2*>(&g_h1h[(size_t)rA * HID + col]) =
                __floats2half2_rn(acc[nt][0], acc[nt][1]);
        if (rB < NN)
            *reinterpret_cast<__half2*>(&g_h1h[(size_t)rB * HID + col]) =
                __floats2half2_rn(acc[nt][2], acc[nt][3]);
    }
}

// ---------------- layer-1 aggregation: warp per dst, 8-edge unrolled ----------
__global__ void __launch_bounds__(256)
k_agg1() {
    int d = blockIdx.x * 8 + (threadIdx.x >> 5);
    if (d >= NN) return;
    int lane = threadIdx.x & 31;
    int start = g_off[d], n = g_count[d];
    float sl = g_selfnorm[d];
    __half2 hv = *reinterpret_cast<const __half2*>(&g_h1h[(size_t)d * HID + lane * 2]);
    float2 v0 = __half22float2(hv);
    float2 acc = make_float2(v0.x * sl, v0.y * sl);
    const int2* ep = g_edge + start;
    int j = 0;
    for (; j + 8 <= n; j += 8) {
        int2 e[8];
        __half2 h[8];
#pragma unroll
        for (int u = 0; u < 8; u++) e[u] = ep[j + u];
#pragma unroll
        for (int u = 0; u < 8; u++)
            h[u] = *reinterpret_cast<const __half2*>(&g_h1h[(size_t)e[u].x * HID + lane * 2]);
#pragma unroll
        for (int u = 0; u < 8; u++) {
            float nm = __int_as_float(e[u].y);
            float2 f = __half22float2(h[u]);
            acc.x = fmaf(f.x, nm, acc.x);
            acc.y = fmaf(f.y, nm, acc.y);
        }
    }
    for (; j < n; j++) {
        int2 ed = ep[j];
        float nm = __int_as_float(ed.y);
        __half2 h = *reinterpret_cast<const __half2*>(&g_h1h[(size_t)ed.x * HID + lane * 2]);
        float2 v = __half22float2(h);
        acc.x = fmaf(v.x, nm, acc.x);
        acc.y = fmaf(v.y, nm, acc.y);
    }
    *reinterpret_cast<float2*>(&g_agg1[(size_t)d * HID + lane * 2]) = acc;
}

// ---------------- GEMM2: relu(agg1+b1) @ W2 -> h2 ----------------------------
__global__ void k_gemm2(const float* __restrict__ b1, const float* __restrict__ W2) {
    __shared__ float w2s[HID * NCLS];
    __shared__ float b1s[HID];
    int tid = threadIdx.x;
    for (int i = tid; i < HID * NCLS; i += blockDim.x) w2s[i] = W2[i];
    if (tid < HID) b1s[tid] = b1[tid];
    __syncthreads();
    int row = blockIdx.x * blockDim.x + tid;
    if (row >= NN) return;
    float acc[NCLS];
#pragma unroll
    for (int c = 0; c < NCLS; c++) acc[c] = 0.0f;
    const float4* arow = reinterpret_cast<const float4*>(&g_agg1[(size_t)row * HID]);
#pragma unroll
    for (int k4 = 0; k4 < HID / 4; k4++) {
        float4 v = arow[k4];
        float z0 = fmaxf(v.x + b1s[4 * k4 + 0], 0.0f);
        float z1 = fmaxf(v.y + b1s[4 * k4 + 1], 0.0f);
        float z2 = fmaxf(v.z + b1s[4 * k4 + 2], 0.0f);
        float z3 = fmaxf(v.w + b1s[4 * k4 + 3], 0.0f);
#pragma unroll
        for (int c = 0; c < NCLS; c++) {
            acc[c] = fmaf(z0, w2s[(4 * k4 + 0) * NCLS + c], acc[c]);
            acc[c] = fmaf(z1, w2s[(4 * k4 + 1) * NCLS + c], acc[c]);
            acc[c] = fmaf(z2, w2s[(4 * k4 + 2) * NCLS + c], acc[c]);
            acc[c] = fmaf(z3, w2s[(4 * k4 + 3) * NCLS + c], acc[c]);
        }
    }
#pragma unroll
    for (int c = 0; c < NCLS; c++) g_h2[(size_t)row * NCLS + c] = acc[c];
}

// ---------------- layer-2 aggregation + bias + log_softmax (fused) ------------
__global__ void __launch_bounds__(256)
k_agg2_sm(const float* __restrict__ b2, float* __restrict__ out) {
    int warp = blockIdx.x * 8 + (threadIdx.x >> 5);
    int lane = threadIdx.x & 31;
    int d = warp * 2 + (lane >> 4);
    int f = lane & 15;
    if (d >= NN) return;
    int start = g_off[d], n = g_count[d];
    float acc = g_h2[(size_t)d * NCLS + f] * g_selfnorm[d];
    const int2* ep = g_edge + start;
    int j = 0;
    for (; j + 4 <= n; j += 4) {
        int2 e0 = ep[j], e1 = ep[j + 1], e2 = ep[j + 2], e3 = ep[j + 3];
        float v0 = g_h2[(size_t)e0.x * NCLS + f];
        float v1 = g_h2[(size_t)e1.x * NCLS + f];
        float v2 = g_h2[(size_t)e2.x * NCLS + f];
        float v3 = g_h2[(size_t)e3.x * NCLS + f];
        acc = fmaf(v0, __int_as_float(e0.y), acc);
        acc = fmaf(v1, __int_as_float(e1.y), acc);
        acc = fmaf(v2, __int_as_float(e2.y), acc);
        acc = fmaf(v3, __int_as_float(e3.y), acc);
    }
    for (; j < n; j++) {
        int2 ed = ep[j];
        acc = fmaf(g_h2[(size_t)ed.x * NCLS + f], __int_as_float(ed.y), acc);
    }
    float v = acc + b2[f];
    float m = v;
#pragma unroll
    for (int msk = 8; msk; msk >>= 1) m = fmaxf(m, __shfl_xor_sync(0xFFFFFFFFu, m, msk));
    float s = expf(v - m);
#pragma unroll
    for (int msk = 8; msk; msk >>= 1) s += __shfl_xor_sync(0xFFFFFFFFu, s, msk);
    out[(size_t)d * NCLS + f] = v - (logf(s) + m);
}

// ---------------- launch ------------------------------------------------------
extern "C" void kernel_launch(void* const* d_in, const int* in_sizes, int n_in,
                              void* d_out, int out_size) {
    const float* x  = (const float*)d_in[0];
    const int*   ei = (const int*)  d_in[1];
    const float* ew = (const float*)d_in[2];
    const float* W1 = (const float*)d_in[3];
    const float* b1 = (const float*)d_in[4];
    const float* W2 = (const float*)d_in[5];
    const float* b2 = (const float*)d_in[6];
    float* out = (float*)d_out;

    const int* src = ei;
    const int* dst = ei + EE;

    k_zero     <<<(NN + 255) / 256, 256>>>();
    k_hist     <<<(EE + 255) / 256, 256>>>(dst, ew);
    k_dis      <<<(NN + 255) / 256, 256>>>();
    k_scan1    <<<NCH, 1024>>>();
    k_scan2    <<<1, 128>>>();
    k_scan3    <<<(NN + 255) / 256, 256>>>();
    k_fill     <<<(EE + 255) / 256, 256>>>(src, dst, ew);
    k_prep_w   <<<(HID * INDIM + 255) / 256, 256>>>(W1);

    k_gemm1_tc <<<(NN + 127) / 128, 256>>>(x);
    k_agg1     <<<(NN + 7) / 8, 256>>>();
    k_gemm2    <<<(NN + 255) / 256, 256>>>(b1, W2);
    k_agg2_sm  <<<(NN / 2 + 7) / 8, 256>>>(b2, out);
}

// round 12
// speedup vs baseline: 2.3904x; 1.0901x over previous
#include <cuda_runtime.h>
#include <cuda_bf16.h>
#include <cuda_fp16.h>
#include <cstdint>

#define NN      100000
#define EE      1600000
#define INDIM   512
#define HID     64
#define NCLS    16
#define NCH     ((NN + 1023) / 1024)     // 98 scan chunks
#define NBZERO  ((NN + 255) / 256)       // zero-blocks in fused init kernel
#define NBPREP  ((HID * INDIM + 255) / 256)

// ---------------- scratch (static device globals; no allocation) -------------
__device__ float g_deg[NN];
__device__ float g_dis[NN];
__device__ float g_selfnorm[NN];
__device__ __half g_h1h[(size_t)NN * HID];
__device__ float g_agg1[(size_t)NN * HID];
__device__ float g_h2[(size_t)NN * NCLS];
__device__ int   g_count[NN];
__device__ int   g_off[NN];
__device__ int   g_cursor[NN];
__device__ int   g_bsum[128];
__device__ int   g_bcarry[128];
__device__ int2  g_edge[EE];             // (src, full-norm bits) sorted by dst
__device__ __half g_w1t_hi[HID * INDIM]; // W1^T fp16 hi, [HID][INDIM]
__device__ __half g_w1t_lo[HID * INDIM]; // W1^T fp16 residual

// ---------------- helpers -----------------------------------------------------
__device__ __forceinline__ void mma_f16(float& d0, float& d1, float& d2, float& d3,
                                        uint32_t a0, uint32_t a1, uint32_t a2, uint32_t a3,
                                        uint32_t b0, uint32_t b1) {
    asm volatile(
        "mma.sync.aligned.m16n8k16.row.col.f32.f16.f16.f32 "
        "{%0,%1,%2,%3}, {%4,%5,%6,%7}, {%8,%9}, {%0,%1,%2,%3};"
        : "+f"(d0), "+f"(d1), "+f"(d2), "+f"(d3)
        : "r"(a0), "r"(a1), "r"(a2), "r"(a3), "r"(b0), "r"(b1));
}

// ---------------- fused init: zero counters + W1^T fp16 split -----------------
__global__ void k_init(const float* __restrict__ W1) {
    if (blockIdx.x < NBZERO) {
        int i = blockIdx.x * 256 + threadIdx.x;
        if (i < NN) { g_count[i] = 0; g_deg[i] = 1.0f; }   // self-loop weight
    } else {
        int idx = (blockIdx.x - NBZERO) * 256 + threadIdx.x;
        if (idx < HID * INDIM) {
            int n = idx >> 9;
            int k = idx & 511;
            float w = W1[k * HID + n];
            __half h = __float2half_rn(w);
            g_w1t_hi[n * INDIM + k] = h;
            g_w1t_lo[n * INDIM + k] = __float2half_rn(w - __half2float(h));
        }
    }
}

// fused: edge histogram + weighted degree
__global__ void k_hist(const int* __restrict__ dst, const float* __restrict__ ew) {
    int e = blockIdx.x * blockDim.x + threadIdx.x;
    if (e < EE) {
        int d = dst[e];
        atomicAdd(&g_count[d], 1);
        atomicAdd(&g_deg[d], ew[e]);
    }
}

// scan chunk + fused dis/selfnorm compute
__global__ void k_scan1() {
    __shared__ int sm[1024];
    int tid = threadIdx.x;
    int i = blockIdx.x * 1024 + tid;
    int v = (i < NN) ? g_count[i] : 0;
    sm[tid] = v;
    __syncthreads();
#pragma unroll
    for (int off = 1; off < 1024; off <<= 1) {
        int t = (tid >= off) ? sm[tid - off] : 0;
        __syncthreads();
        sm[tid] += t;
        __syncthreads();
    }
    if (i < NN) {
        g_off[i] = sm[tid] - v;
        float r = rsqrtf(g_deg[i]);       // deg ready (k_hist done)
        g_dis[i] = r;
        g_selfnorm[i] = r * r;
    }
    if (tid == 1023) g_bsum[blockIdx.x] = sm[tid];
}

__global__ void k_scan2() {
    __shared__ int sm[128];
    int tid = threadIdx.x;
    int v = (tid < NCH) ? g_bsum[tid] : 0;
    sm[tid] = v;
    __syncthreads();
#pragma unroll
    for (int off = 1; off < 128; off <<= 1) {
        int t = (tid >= off) ? sm[tid - off] : 0;
        __syncthreads();
        sm[tid] += t;
        __syncthreads();
    }
    g_bcarry[tid] = sm[tid] - v;
}

__global__ void k_scan3() {
    int i = blockIdx.x * blockDim.x + threadIdx.x;
    if (i < NN) {
        int o = g_off[i] + g_bcarry[i >> 10];
        g_off[i] = o;
        g_cursor[i] = o;
    }
}

// fill with FULL norm dis[src]*w*dis[dst]
__global__ void k_fill(const int* __restrict__ src, const int* __restrict__ dst,
                       const float* __restrict__ ew) {
    int e = blockIdx.x * blockDim.x + threadIdx.x;
    if (e >= EE) return;
    int s = src[e], d = dst[e];
    int pos = atomicAdd(&g_cursor[d], 1);
    float nm = g_dis[s] * ew[e] * g_dis[d];
    g_edge[pos] = make_int2(s, __float_as_int(nm));
}

// ---------------- GEMM1: fp16 mma.sync, W split hi/lo, x single fp16 ----------
// D = x_f16 * (Whi + Wlo)  -> corrects W truncation; only x's 2^-12 remains.
#define KC     32
#define APITCH 40
#define APB    (APITCH * 2)

__global__ void __launch_bounds__(256)
k_gemm1_tc(const float* __restrict__ x) {
    __shared__ uint8_t As  [128 * APB];
    __shared__ uint8_t Bs_hi[64 * APB];
    __shared__ uint8_t Bs_lo[64 * APB];

    int tid = threadIdx.x;
    int wid = tid >> 5;
    int lane = tid & 31;
    int lt = lane >> 2;
    int q  = lane & 3;
    int row0 = blockIdx.x * 128;

    float acc[8][4];
#pragma unroll
    for (int t = 0; t < 8; t++)
#pragma unroll
        for (int j = 0; j < 4; j++) acc[t][j] = 0.0f;

    const uint2* whi = reinterpret_cast<const uint2*>(g_w1t_hi);
    const uint2* wlo = reinterpret_cast<const uint2*>(g_w1t_lo);

    float4 vx[4];
    uint2  vbh[2], vbl[2];

    auto load_g = [&](int k0) {
#pragma unroll
        for (int i = 0; i < 4; i++) {
            int idx = tid + i * 256;
            int r = idx >> 3;
            int c4 = (idx & 7) * 4;
            int grow = row0 + r;
            vx[i] = (grow < NN)
                ? *reinterpret_cast<const float4*>(&x[(size_t)grow * INDIM + k0 + c4])
                : make_float4(0.f, 0.f, 0.f, 0.f);
        }
#pragma unroll
        for (int i = 0; i < 2; i++) {
            int idx = tid + i * 256;
            int n = idx >> 3;
            int j = idx & 7;
            int gidx = n * 128 + (k0 >> 2) + j;
            vbh[i] = whi[gidx];
            vbl[i] = wlo[gidx];
        }
    };

    auto store_s = [&]() {
#pragma unroll
        for (int i = 0; i < 4; i++) {
            int idx = tid + i * 256;
            int r = idx >> 3;
            int c4 = (idx & 7) * 4;
            float4 v = vx[i];
            __half2 p0 = __floats2half2_rn(v.x, v.y);
            __half2 p1 = __floats2half2_rn(v.z, v.w);
            uint32_t off = (uint32_t)(r * APB + c4 * 2);
            *reinterpret_cast<uint2*>(As + off) =
                make_uint2(*reinterpret_cast<uint32_t*>(&p0),
                           *reinterpret_cast<uint32_t*>(&p1));
        }
#pragma unroll
        for (int i = 0; i < 2; i++) {
            int idx = tid + i * 256;
            int n = idx >> 3;
            int j = idx & 7;
            uint32_t off = (uint32_t)(n * APB + j * 8);
            *reinterpret_cast<uint2*>(Bs_hi + off) = vbh[i];
            *reinterpret_cast<uint2*>(Bs_lo + off) = vbl[i];
        }
    };

    load_g(0);
    store_s();
    __syncthreads();

    for (int c = 0; c < INDIM / KC; c++) {
        bool more = (c + 1 < INDIM / KC);
        if (more) load_g((c + 1) * KC);

#pragma unroll
        for (int ks = 0; ks < 2; ks++) {
            uint32_t abase = (uint32_t)((wid * 16 + lt) * APB + ks * 32 + q * 4);
            uint32_t a0 = *reinterpret_cast<const uint32_t*>(As + abase);
            uint32_t a1 = *reinterpret_cast<const uint32_t*>(As + abase + 8 * APB);
            uint32_t a2 = *reinterpret_cast<const uint32_t*>(As + abase + 16);
            uint32_t a3 = *reinterpret_cast<const uint32_t*>(As + abase + 8 * APB + 16);
#pragma unroll
            for (int nt = 0; nt < 8; nt++) {
                uint32_t bbase = (uint32_t)((nt * 8 + lt) * APB + ks * 32 + q * 4);
                uint32_t bh0 = *reinterpret_cast<const uint32_t*>(Bs_hi + bbase);
                uint32_t bh1 = *reinterpret_cast<const uint32_t*>(Bs_hi + bbase + 16);
                uint32_t bl0 = *reinterpret_cast<const uint32_t*>(Bs_lo + bbase);
                uint32_t bl1 = *reinterpret_cast<const uint32_t*>(Bs_lo + bbase + 16);
                mma_f16(acc[nt][0], acc[nt][1], acc[nt][2], acc[nt][3],
                        a0, a1, a2, a3, bh0, bh1);
                mma_f16(acc[nt][0], acc[nt][1], acc[nt][2], acc[nt][3],
                        a0, a1, a2, a3, bl0, bl1);
            }
        }
        __syncthreads();
        if (more) {
            store_s();
            __syncthreads();
        }
    }

    int rA = row0 + wid * 16 + lt;
    int rB = rA + 8;
#pragma unroll
    for (int nt = 0; nt < 8; nt++) {
        int col = nt * 8 + q * 2;
        if (rA < NN)
            *reinterpret_cast<__half2*>(&g_h1h[(size_t)rA * HID + col]) =
                __floats2half2_rn(acc[nt][0], acc[nt][1]);
        if (rB < NN)
            *reinterpret_cast<__half2*>(&g_h1h[(size_t)rB * HID + col]) =
                __floats2half2_rn(acc[nt][2], acc[nt][3]);
    }
}

// ---------------- layer-1 aggregation: warp per dst, 8-edge unrolled ----------
__global__ void __launch_bounds__(256)
k_agg1() {
    int d = blockIdx.x * 8 + (threadIdx.x >> 5);
    if (d >= NN) return;
    int lane = threadIdx.x & 31;
    int start = g_off[d], n = g_count[d];
    float sl = g_selfnorm[d];
    __half2 hv = *reinterpret_cast<const __half2*>(&g_h1h[(size_t)d * HID + lane * 2]);
    float2 v0 = __half22float2(hv);
    float2 acc = make_float2(v0.x * sl, v0.y * sl);
    const int2* ep = g_edge + start;
    int j = 0;
    for (; j + 8 <= n; j += 8) {
        int2 e[8];
        __half2 h[8];
#pragma unroll
        for (int u = 0; u < 8; u++) e[u] = ep[j + u];
#pragma unroll
        for (int u = 0; u < 8; u++)
            h[u] = *reinterpret_cast<const __half2*>(&g_h1h[(size_t)e[u].x * HID + lane * 2]);
#pragma unroll
        for (int u = 0; u < 8; u++) {
            float nm = __int_as_float(e[u].y);
            float2 f = __half22float2(h[u]);
            acc.x = fmaf(f.x, nm, acc.x);
            acc.y = fmaf(f.y, nm, acc.y);
        }
    }
    for (; j < n; j++) {
        int2 ed = ep[j];
        float nm = __int_as_float(ed.y);
        __half2 h = *reinterpret_cast<const __half2*>(&g_h1h[(size_t)ed.x * HID + lane * 2]);
        float2 v = __half22float2(h);
        acc.x = fmaf(v.x, nm, acc.x);
        acc.y = fmaf(v.y, nm, acc.y);
    }
    *reinterpret_cast<float2*>(&g_agg1[(size_t)d * HID + lane * 2]) = acc;
}

// ---------------- GEMM2: relu(agg1+b1) @ W2 -> h2 ----------------------------
__global__ void k_gemm2(const float* __restrict__ b1, const float* __restrict__ W2) {
    __shared__ float w2s[HID * NCLS];
    __shared__ float b1s[HID];
    int tid = threadIdx.x;
    for (int i = tid; i < HID * NCLS; i += blockDim.x) w2s[i] = W2[i];
    if (tid < HID) b1s[tid] = b1[tid];
    __syncthreads();
    int row = blockIdx.x * blockDim.x + tid;
    if (row >= NN) return;
    float acc[NCLS];
#pragma unroll
    for (int c = 0; c < NCLS; c++) acc[c] = 0.0f;
    const float4* arow = reinterpret_cast<const float4*>(&g_agg1[(size_t)row * HID]);
#pragma unroll
    for (int k4 = 0; k4 < HID / 4; k4++) {
        float4 v = arow[k4];
        float z0 = fmaxf(v.x + b1s[4 * k4 + 0], 0.0f);
        float z1 = fmaxf(v.y + b1s[4 * k4 + 1], 0.0f);
        float z2 = fmaxf(v.z + b1s[4 * k4 + 2], 0.0f);
        float z3 = fmaxf(v.w + b1s[4 * k4 + 3], 0.0f);
#pragma unroll
        for (int c = 0; c < NCLS; c++) {
            acc[c] = fmaf(z0, w2s[(4 * k4 + 0) * NCLS + c], acc[c]);
            acc[c] = fmaf(z1, w2s[(4 * k4 + 1) * NCLS + c], acc[c]);
            acc[c] = fmaf(z2, w2s[(4 * k4 + 2) * NCLS + c], acc[c]);
            acc[c] = fmaf(z3, w2s[(4 * k4 + 3) * NCLS + c], acc[c]);
        }
    }
#pragma unroll
    for (int c = 0; c < NCLS; c++) g_h2[(size_t)row * NCLS + c] = acc[c];
}

// ---------------- layer-2 aggregation + bias + log_softmax (fused) ------------
__global__ void __launch_bounds__(256)
k_agg2_sm(const float* __restrict__ b2, float* __restrict__ out) {
    int warp = blockIdx.x * 8 + (threadIdx.x >> 5);
    int lane = threadIdx.x & 31;
    int d = warp * 2 + (lane >> 4);
    int f = lane & 15;
    if (d >= NN) return;
    int start = g_off[d], n = g_count[d];
    float acc = g_h2[(size_t)d * NCLS + f] * g_selfnorm[d];
    const int2* ep = g_edge + start;
    int j = 0;
    for (; j + 4 <= n; j += 4) {
        int2 e0 = ep[j], e1 = ep[j + 1], e2 = ep[j + 2], e3 = ep[j + 3];
        float v0 = g_h2[(size_t)e0.x * NCLS + f];
        float v1 = g_h2[(size_t)e1.x * NCLS + f];
        float v2 = g_h2[(size_t)e2.x * NCLS + f];
        float v3 = g_h2[(size_t)e3.x * NCLS + f];
        acc = fmaf(v0, __int_as_float(e0.y), acc);
        acc = fmaf(v1, __int_as_float(e1.y), acc);
        acc = fmaf(v2, __int_as_float(e2.y), acc);
        acc = fmaf(v3, __int_as_float(e3.y), acc);
    }
    for (; j < n; j++) {
        int2 ed = ep[j];
        acc = fmaf(g_h2[(size_t)ed.x * NCLS + f], __int_as_float(ed.y), acc);
    }
    float v = acc + b2[f];
    float m = v;
#pragma unroll
    for (int msk = 8; msk; msk >>= 1) m = fmaxf(m, __shfl_xor_sync(0xFFFFFFFFu, m, msk));
    float s = expf(v - m);
#pragma unroll
    for (int msk = 8; msk; msk >>= 1) s += __shfl_xor_sync(0xFFFFFFFFu, s, msk);
    out[(size_t)d * NCLS + f] = v - (logf(s) + m);
}

// ---------------- launch ------------------------------------------------------
extern "C" void kernel_launch(void* const* d_in, const int* in_sizes, int n_in,
                              void* d_out, int out_size) {
    const float* x  = (const float*)d_in[0];
    const int*   ei = (const int*)  d_in[1];
    const float* ew = (const float*)d_in[2];
    const float* W1 = (const float*)d_in[3];
    const float* b1 = (const float*)d_in[4];
    const float* W2 = (const float*)d_in[5];
    const float* b2 = (const float*)d_in[6];
    float* out = (float*)d_out;

    const int* src = ei;
    const int* dst = ei + EE;

    k_init     <<<NBZERO + NBPREP, 256>>>(W1);
    k_hist     <<<(EE + 255) / 256, 256>>>(dst, ew);
    k_scan1    <<<NCH, 1024>>>();
    k_scan2    <<<1, 128>>>();
    k_scan3    <<<(NN + 255) / 256, 256>>>();
    k_fill     <<<(EE + 255) / 256, 256>>>(src, dst, ew);

    k_gemm1_tc <<<(NN + 127) / 128, 256>>>(x);
    k_agg1     <<<(NN + 7) / 8, 256>>>();
    k_gemm2    <<<(NN + 255) / 256, 256>>>(b1, W2);
    k_agg2_sm  <<<(NN / 2 + 7) / 8, 256>>>(b2, out);
}